// round 5
// baseline (speedup 1.0000x reference)
#include <cuda_runtime.h>
#include <cstddef>

#define B_ 16
#define N_ 512
#define T_ 24
#define F_ 64
#define BT_ (B_*T_)
#define ROWS 32

__device__ float g_E[N_*N_];
__device__ float g_xw[(size_t)BT_*N_*F_];
__device__ float g_uw[(size_t)BT_*N_*F_];

// E = emb @ emb^T. grid 16x8 tiles of 32x64.
__global__ void kA(const float* __restrict__ emb) {
    __shared__ float rb[ROWS*F_];
    __shared__ float cb[64*65];
    int bi = blockIdx.x >> 3, bj = blockIdx.x & 7;
    int tid = threadIdx.x;
    for (int i = tid; i < ROWS*F_; i += 256) rb[i] = emb[(bi*ROWS + (i>>6))*F_ + (i&63)];
    for (int i = tid; i < 64*F_; i += 256) cb[(i>>6)*65 + (i&63)] = emb[(bj*64 + (i>>6))*F_ + (i&63)];
    __syncthreads();
    int ty = tid >> 5, tx = tid & 31;
    float acc[4][2] = {};
    for (int k = 0; k < F_; k++) {
        float b0 = cb[tx*65+k], b1 = cb[(tx+32)*65+k];
        #pragma unroll
        for (int i = 0; i < 4; i++) {
            float a = rb[(ty*4+i)*F_ + k];
            acc[i][0] += a*b0; acc[i][1] += a*b1;
        }
    }
    for (int i = 0; i < 4; i++) {
        int r = bi*ROWS + ty*4 + i;
        g_E[r*N_ + bj*64 + tx]      = acc[i][0];
        g_E[r*N_ + bj*64 + tx + 32] = acc[i][1];
    }
}

// XW = x@W1^T, UW = u@W1^T per slice. grid = BT_*16.
__global__ void kB(const float* __restrict__ ori, const float* __restrict__ unc,
                   const float* __restrict__ W1) {
    __shared__ float w[64*65];
    __shared__ float xr[ROWS*F_], ur[ROWS*F_];
    int bt = blockIdx.x >> 4, nb = blockIdx.x & 15;
    int b = bt / T_, t = bt % T_;
    int n0 = nb * ROWS;
    int tid = threadIdx.x;
    for (int i = tid; i < 64*64; i += 256) w[(i>>6)*65 + (i&63)] = W1[i];
    for (int i = tid; i < ROWS*F_; i += 256) {
        size_t g = ((size_t)(b*N_ + n0 + (i>>6))*T_ + t)*F_ + (i&63);
        xr[i] = ori[g]; ur[i] = unc[g];
    }
    __syncthreads();
    int ty = tid>>5, tx = tid&31;
    float ax[4][2] = {}, au[4][2] = {};
    for (int k = 0; k < F_; k++) {
        float b0 = w[tx*65+k], b1 = w[(tx+32)*65+k];
        #pragma unroll
        for (int i = 0; i < 4; i++) {
            float a = xr[(ty*4+i)*F_+k], c = ur[(ty*4+i)*F_+k];
            ax[i][0] += a*b0; ax[i][1] += a*b1;
            au[i][0] += c*b0; au[i][1] += c*b1;
        }
    }
    size_t so = (size_t)bt*N_*F_;
    for (int i = 0; i < 4; i++) {
        int n = n0 + ty*4 + i;
        g_xw[so + n*F_ + tx]    = ax[i][0];
        g_xw[so + n*F_ + tx+32] = ax[i][1];
        g_uw[so + n*F_ + tx]    = au[i][0];
        g_uw[so + n*F_ + tx+32] = au[i][1];
    }
}

// Fused attention: S=x@x^T+E, P=softmax(relu(S)), out=relu(P@V)/l. grid = BT_*16.
__global__ void kC(const float* __restrict__ ori, float* __restrict__ out_of,
                   float* __restrict__ out_uf) {
    extern __shared__ float sm[];
    float* S  = sm;                   // 32*512
    float* rb = sm + ROWS*N_;         // 32*64
    float* kb = rb + ROWS*F_;         // 64*65
    float* ls = kb + 64*65;           // 32
    int bt = blockIdx.x >> 4, nb = blockIdx.x & 15;
    int b = bt / T_, t = bt % T_;
    int n0 = nb*ROWS;
    int tid = threadIdx.x, ty = tid>>5, tx = tid&31;
    for (int i = tid; i < ROWS*F_; i += 256) {
        size_t g = ((size_t)(b*N_ + n0 + (i>>6))*T_ + t)*F_ + (i&63);
        rb[i] = ori[g];
    }
    for (int kt = 0; kt < 8; kt++) {
        __syncthreads();
        for (int i = tid; i < 64*F_; i += 256) {
            size_t g = ((size_t)(b*N_ + kt*64 + (i>>6))*T_ + t)*F_ + (i&63);
            kb[(i>>6)*65 + (i&63)] = ori[g];
        }
        __syncthreads();
        float acc[4][2] = {};
        for (int k = 0; k < F_; k++) {
            float b0 = kb[tx*65+k], b1 = kb[(tx+32)*65+k];
            #pragma unroll
            for (int i = 0; i < 4; i++) {
                float a = rb[(ty*4+i)*F_+k];
                acc[i][0] += a*b0; acc[i][1] += a*b1;
            }
        }
        for (int i = 0; i < 4; i++) {
            S[(ty*4+i)*N_ + kt*64 + tx]    = acc[i][0];
            S[(ty*4+i)*N_ + kt*64 + tx+32] = acc[i][1];
        }
    }
    __syncthreads();
    {   // softmax(relu(S+E)) per row; 8 threads/row
        int row = tid>>3, idx = tid&7;
        const float* Erow = g_E + (size_t)(n0+row)*N_;
        float m = 0.f;
        for (int k = idx; k < N_; k += 8) {
            float v = S[row*N_+k] + Erow[k];
            v = v > 0.f ? v : 0.f;
            S[row*N_+k] = v;
            m = fmaxf(m, v);
        }
        m = fmaxf(m, __shfl_xor_sync(0xffffffffu, m, 1));
        m = fmaxf(m, __shfl_xor_sync(0xffffffffu, m, 2));
        m = fmaxf(m, __shfl_xor_sync(0xffffffffu, m, 4));
        float l = 0.f;
        for (int k = idx; k < N_; k += 8) {
            float p = __expf(S[row*N_+k] - m);
            S[row*N_+k] = p;
            l += p;
        }
        l += __shfl_xor_sync(0xffffffffu, l, 1);
        l += __shfl_xor_sync(0xffffffffu, l, 2);
        l += __shfl_xor_sync(0xffffffffu, l, 4);
        if (idx == 0) ls[row] = l;
    }
    float ao[4][2] = {}, au[4][2] = {};
    size_t so = (size_t)bt*N_*F_;
    #pragma unroll
    for (int br = 0; br < 2; br++) {
        const float* V = br ? g_uw : g_xw;
        for (int kt = 0; kt < 8; kt++) {
            __syncthreads();
            for (int i = tid; i < 64*F_; i += 256)
                kb[(i>>6)*65 + (i&63)] = V[so + (size_t)(kt*64 + (i>>6))*F_ + (i&63)];
            __syncthreads();
            for (int k = 0; k < 64; k++) {
                float b0 = kb[k*65+tx], b1 = kb[k*65+tx+32];
                #pragma unroll
                for (int i = 0; i < 4; i++) {
                    float a = S[(ty*4+i)*N_ + kt*64 + k];
                    if (br) { au[i][0] += a*b0; au[i][1] += a*b1; }
                    else    { ao[i][0] += a*b0; ao[i][1] += a*b1; }
                }
            }
        }
    }
    for (int i = 0; i < 4; i++) {
        int r = ty*4+i;
        float inv = 1.f / ls[r];
        size_t g = ((size_t)(b*N_ + n0 + r)*T_ + t)*F_;
        out_of[g+tx]    = fmaxf(ao[i][0], 0.f)*inv;
        out_of[g+tx+32] = fmaxf(ao[i][1], 0.f)*inv;
        out_uf[g+tx]    = fmaxf(au[i][0], 0.f)*inv;
        out_uf[g+tx+32] = fmaxf(au[i][1], 0.f)*inv;
    }
}

extern "C" void kernel_launch(void* const* d_in, const int* in_sizes, int n_in,
                              void* d_out, int out_size) {
    const float* ori = (const float*)d_in[0];
    const float* unc = (const float*)d_in[1];
    const float* emb = (const float*)d_in[2];
    const float* W1  = (const float*)d_in[3];
    float* out   = (float*)d_out;
    float* outuf = out + (size_t)out_size/2;
    int smemC = (ROWS*N_ + ROWS*F_ + 64*65 + 32) * 4;
    cudaFuncSetAttribute(kC, cudaFuncAttributeMaxDynamicSharedMemorySize, smemC);
    kA<<<128, 256>>>(emb);
    kB<<<BT_*16, 256>>>(ori, unc, W1);
    kC<<<BT_*16, 256, smemC>>>(ori, out, outuf);
}

// round 7
// speedup vs baseline: 1.3885x; 1.3885x over previous
#include <cuda_runtime.h>
#include <cstddef>

#define B_ 16
#define N_ 512
#define T_ 24
#define F_ 64
#define BT_ (B_*T_)
#define SS 516   // padded S stride

__device__ float g_E[N_*N_];
__device__ float g_xw[(size_t)BT_*N_*F_];
__device__ float g_uw[(size_t)BT_*N_*F_];

// E = emb @ emb^T. grid 16x8 tiles of 32x64.
__global__ void kA(const float* __restrict__ emb) {
    __shared__ float rb[32*F_];
    __shared__ float cb[64*65];
    int bi = blockIdx.x >> 3, bj = blockIdx.x & 7;
    int tid = threadIdx.x;
    for (int i = tid; i < 32*F_; i += 256) rb[i] = emb[(bi*32 + (i>>6))*F_ + (i&63)];
    for (int i = tid; i < 64*F_; i += 256) cb[(i>>6)*65 + (i&63)] = emb[(bj*64 + (i>>6))*F_ + (i&63)];
    __syncthreads();
    int ty = tid >> 5, tx = tid & 31;
    float acc[4][2] = {};
    for (int k = 0; k < F_; k++) {
        float b0 = cb[tx*65+k], b1 = cb[(tx+32)*65+k];
        #pragma unroll
        for (int i = 0; i < 4; i++) {
            float a = rb[(ty*4+i)*F_ + k];
            acc[i][0] += a*b0; acc[i][1] += a*b1;
        }
    }
    for (int i = 0; i < 4; i++) {
        int r = bi*32 + ty*4 + i;
        g_E[r*N_ + bj*64 + tx]      = acc[i][0];
        g_E[r*N_ + bj*64 + tx + 32] = acc[i][1];
    }
}

// XW = x@W1^T, UW = u@W1^T. grid = BT_*8, 64 rows per CTA.
__global__ void __launch_bounds__(256) kB(const float* __restrict__ ori,
                                          const float* __restrict__ unc,
                                          const float* __restrict__ W1) {
    __shared__ float wT[64*64];          // wT[k*64+o] = W1[o*64+k]
    __shared__ float xr[64*F_], ur[64*F_];
    int bt = blockIdx.x >> 3, nb = blockIdx.x & 7;
    int b = bt / T_, t = bt % T_;
    int n0 = nb * 64;
    int tid = threadIdx.x;
    for (int i = tid; i < 64*64; i += 256) wT[(i&63)*64 + (i>>6)] = W1[i];
    {
        int r = tid >> 2, f4 = tid & 3;  // 256 threads -> 64 rows x 4 float4
        size_t g = ((size_t)(b*N_ + n0 + r)*T_ + t)*F_;
        #pragma unroll
        for (int j = 0; j < 4; j++) {
            int f = (f4*4 + j*16);
            *(float4*)&xr[r*F_ + f] = *(const float4*)&ori[g + f];
            *(float4*)&ur[r*F_ + f] = *(const float4*)&unc[g + f];
        }
    }
    __syncthreads();
    int ty = tid>>5, tx = tid&31;
    float ax[8][2] = {}, au[8][2] = {};
    for (int k = 0; k < F_; k += 4) {
        float4 a4x[8], a4u[8];
        #pragma unroll
        for (int i = 0; i < 8; i++) {
            a4x[i] = *(float4*)&xr[(ty*8+i)*F_ + k];
            a4u[i] = *(float4*)&ur[(ty*8+i)*F_ + k];
        }
        #pragma unroll
        for (int kk = 0; kk < 4; kk++) {
            float b0 = wT[(k+kk)*64 + tx], b1 = wT[(k+kk)*64 + tx+32];
            #pragma unroll
            for (int i = 0; i < 8; i++) {
                float axe = kk==0?a4x[i].x:kk==1?a4x[i].y:kk==2?a4x[i].z:a4x[i].w;
                float aue = kk==0?a4u[i].x:kk==1?a4u[i].y:kk==2?a4u[i].z:a4u[i].w;
                ax[i][0] += axe*b0; ax[i][1] += axe*b1;
                au[i][0] += aue*b0; au[i][1] += aue*b1;
            }
        }
    }
    size_t so = (size_t)bt*N_*F_;
    for (int i = 0; i < 8; i++) {
        int n = n0 + ty*8 + i;
        g_xw[so + n*F_ + tx]    = ax[i][0];
        g_xw[so + n*F_ + tx+32] = ax[i][1];
        g_uw[so + n*F_ + tx]    = au[i][0];
        g_uw[so + n*F_ + tx+32] = au[i][1];
    }
}

// Fused attention. grid = BT_*8, 64 rows per CTA.
__global__ void __launch_bounds__(256) kC(const float* __restrict__ ori,
                                          float* __restrict__ out_of,
                                          float* __restrict__ out_uf) {
    extern __shared__ float sm[];
    float* S  = sm;                       // 64*516
    float* V0 = sm + 64*SS;               // 128*65 (aliases rb in S phase)
    float* V1 = V0 + 128*65;              // 128*65 (aliases kb in S phase)
    float* ls = V1 + 128*65;              // 64
    float* rb = V0;                       // 64*64 x-rows
    float* kb = V1;                       // 128*65 key tile
    int bt = blockIdx.x >> 3, nb = blockIdx.x & 7;
    int b = bt / T_, t = bt % T_;
    int n0 = nb*64;
    int tid = threadIdx.x, ty = tid>>5, tx = tid&31;

    {   // load 64 query rows (float4)
        int r = tid >> 2, f4 = tid & 3;
        size_t g = ((size_t)(b*N_ + n0 + r)*T_ + t)*F_;
        #pragma unroll
        for (int j = 0; j < 4; j++) {
            int f = f4*4 + j*16;
            *(float4*)&rb[r*F_ + f] = *(const float4*)&ori[g + f];
        }
    }
    // ---- S = x@x^T over 4 key tiles of 128 ----
    for (int kt = 0; kt < 4; kt++) {
        __syncthreads();
        for (int i = tid; i < 128*16; i += 256) {   // 128 rows x 16 float4
            int r = i >> 4, f = (i & 15)*4;
            size_t g = ((size_t)(b*N_ + kt*128 + r)*T_ + t)*F_ + f;
            float4 v = *(const float4*)&ori[g];
            kb[r*65 + f]   = v.x; kb[r*65 + f+1] = v.y;
            kb[r*65 + f+2] = v.z; kb[r*65 + f+3] = v.w;
        }
        __syncthreads();
        float acc[8][4] = {};
        for (int k = 0; k < F_; k += 4) {
            float4 a4[8];
            #pragma unroll
            for (int i = 0; i < 8; i++) a4[i] = *(float4*)&rb[(ty*8+i)*F_ + k];
            #pragma unroll
            for (int kk = 0; kk < 4; kk++) {
                float bv[4];
                #pragma unroll
                for (int j = 0; j < 4; j++) bv[j] = kb[(tx+32*j)*65 + k + kk];
                #pragma unroll
                for (int i = 0; i < 8; i++) {
                    float a = kk==0?a4[i].x:kk==1?a4[i].y:kk==2?a4[i].z:a4[i].w;
                    #pragma unroll
                    for (int j = 0; j < 4; j++) acc[i][j] += a*bv[j];
                }
            }
        }
        for (int i = 0; i < 8; i++)
            #pragma unroll
            for (int j = 0; j < 4; j++)
                S[(ty*8+i)*SS + kt*128 + tx + 32*j] = acc[i][j];
    }
    __syncthreads();
    {   // relu(S+E) -> softmax numerator; 4 threads per row
        int row = tid>>2, idx = tid&3;
        const float* Erow = g_E + (size_t)(n0+row)*N_;
        float* Srow = S + row*SS;
        float m = 0.f;
        for (int k = idx; k < N_; k += 4) {
            float v = Srow[k] + Erow[k];
            v = v > 0.f ? v : 0.f;
            Srow[k] = v;
            m = fmaxf(m, v);
        }
        m = fmaxf(m, __shfl_xor_sync(0xffffffffu, m, 1));
        m = fmaxf(m, __shfl_xor_sync(0xffffffffu, m, 2));
        float l = 0.f;
        for (int k = idx; k < N_; k += 4) {
            float p = __expf(Srow[k] - m);
            Srow[k] = p;
            l += p;
        }
        l += __shfl_xor_sync(0xffffffffu, l, 1);
        l += __shfl_xor_sync(0xffffffffu, l, 2);
        if (idx == 0) ls[row] = l;
    }
    // ---- P@XW and P@UW over 4 key tiles of 128 ----
    float ao[8][2] = {}, au[8][2] = {};
    size_t so = (size_t)bt*N_*F_;
    for (int kt = 0; kt < 4; kt++) {
        __syncthreads();
        for (int i = tid; i < 128*16; i += 256) {
            int r = i >> 4, f = (i & 15)*4;
            size_t g = so + (size_t)(kt*128 + r)*F_ + f;
            float4 v0 = *(const float4*)&g_xw[g];
            float4 v1 = *(const float4*)&g_uw[g];
            V0[r*65+f] = v0.x; V0[r*65+f+1] = v0.y; V0[r*65+f+2] = v0.z; V0[r*65+f+3] = v0.w;
            V1[r*65+f] = v1.x; V1[r*65+f+1] = v1.y; V1[r*65+f+2] = v1.z; V1[r*65+f+3] = v1.w;
        }
        __syncthreads();
        for (int k = 0; k < 128; k += 4) {
            float4 a4[8];
            #pragma unroll
            for (int i = 0; i < 8; i++) a4[i] = *(float4*)&S[(ty*8+i)*SS + kt*128 + k];
            #pragma unroll
            for (int kk = 0; kk < 4; kk++) {
                float b0 = V0[(k+kk)*65 + tx], b1 = V0[(k+kk)*65 + tx+32];
                float c0 = V1[(k+kk)*65 + tx], c1 = V1[(k+kk)*65 + tx+32];
                #pragma unroll
                for (int i = 0; i < 8; i++) {
                    float a = kk==0?a4[i].x:kk==1?a4[i].y:kk==2?a4[i].z:a4[i].w;
                    ao[i][0] += a*b0; ao[i][1] += a*b1;
                    au[i][0] += a*c0; au[i][1] += a*c1;
                }
            }
        }
    }
    for (int i = 0; i < 8; i++) {
        int r = ty*8+i;
        float inv = 1.f / ls[r];
        size_t g = ((size_t)(b*N_ + n0 + r)*T_ + t)*F_;
        out_of[g+tx]    = fmaxf(ao[i][0], 0.f)*inv;
        out_of[g+tx+32] = fmaxf(ao[i][1], 0.f)*inv;
        out_uf[g+tx]    = fmaxf(au[i][0], 0.f)*inv;
        out_uf[g+tx+32] = fmaxf(au[i][1], 0.f)*inv;
    }
}

extern "C" void kernel_launch(void* const* d_in, const int* in_sizes, int n_in,
                              void* d_out, int out_size) {
    const float* ori = (const float*)d_in[0];
    const float* unc = (const float*)d_in[1];
    const float* emb = (const float*)d_in[2];
    const float* W1  = (const float*)d_in[3];
    float* out   = (float*)d_out;
    float* outuf = out + (size_t)out_size/2;
    int smemC = (64*SS + 2*128*65 + 64) * 4;
    cudaFuncSetAttribute(kC, cudaFuncAttributeMaxDynamicSharedMemorySize, smemC);
    kA<<<128, 256>>>(emb);
    kB<<<BT_*8, 256>>>(ori, unc, W1);
    kC<<<BT_*8, 256, smemC>>>(ori, out, outuf);
}